// round 1
// baseline (speedup 1.0000x reference)
#include <cuda_runtime.h>
#include <cuda_bf16.h>
#include <cstdint>
#include <cstddef>

#define HID 128
#define MAX_NODES 100096  // padded to multiple of BLOCK_M

// Precomputed table: row n = [emb[n]@W1[:128]+b1  |  emb[n]@W1[128:]]
__device__ float g_table[(size_t)MAX_NODES * 256];
__device__ int g_is64;

// ---------------------------------------------------------------------------
// helpers
// ---------------------------------------------------------------------------
__device__ __forceinline__ uint32_t f2tf(float x) {
    uint32_t r;
    asm("cvt.rna.tf32.f32 %0, %1;" : "=r"(r) : "f"(x));
    return r;
}

__device__ __forceinline__ void mma_tf32(float* d, const uint32_t* a, const uint32_t* b) {
    asm volatile(
        "mma.sync.aligned.m16n8k8.row.col.f32.tf32.tf32.f32 "
        "{%0,%1,%2,%3}, {%4,%5,%6,%7}, {%8,%9}, {%0,%1,%2,%3};\n"
        : "+f"(d[0]), "+f"(d[1]), "+f"(d[2]), "+f"(d[3])
        : "r"(a[0]), "r"(a[1]), "r"(a[2]), "r"(a[3]), "r"(b[0]), "r"(b[1]));
}

// ---------------------------------------------------------------------------
// Precompute: T[n][256] = [emb@W1[:128]+b1 | emb@W1[128:]]
// Block tile: 128 rows (M) x 64 cols (N), K = 128 fully resident.
// 8 warps: 4 (M, 32 rows each) x 2 (N, 32 cols each).
// 3xTF32: hi/lo split stored once in smem, acc += ah*bh + al*bh + ah*bl.
// ---------------------------------------------------------------------------
#define BLOCK_M 128
#define BLOCK_N 64
#define SA_STRIDE 132   // 128 + 4 pad -> conflict-free A-frag loads
#define SB_STRIDE 72    // 64 + 8 pad  -> conflict-free B-frag loads
#define SA_ELE (BLOCK_M * SA_STRIDE)
#define SB_ELE (HID * SB_STRIDE)
#define SMEM_BYTES ((2 * SA_ELE + 2 * SB_ELE) * 4)   // 208896 B

__global__ void __launch_bounds__(256) precompute_kernel(
    const float* __restrict__ emb, const float* __restrict__ W1,
    const float* __restrict__ b1, int n_nodes)
{
    extern __shared__ uint32_t sm[];
    uint32_t* sAhi = sm;
    uint32_t* sAlo = sm + SA_ELE;
    uint32_t* sBhi = sm + 2 * SA_ELE;
    uint32_t* sBlo = sm + 2 * SA_ELE + SB_ELE;

    const int tid = threadIdx.x;
    const int m0 = blockIdx.x * BLOCK_M;
    const int by = blockIdx.y;

    // ---- fill A tile (128 rows x 128 K), hi/lo split ----
    for (int i = tid; i < BLOCK_M * HID / 4; i += 256) {
        int row = i >> 5;            // 32 float4 per row
        int c4 = (i & 31) * 4;
        float4 v = make_float4(0.f, 0.f, 0.f, 0.f);
        if (m0 + row < n_nodes)
            v = *reinterpret_cast<const float4*>(emb + (size_t)(m0 + row) * HID + c4);
        float xs[4] = {v.x, v.y, v.z, v.w};
#pragma unroll
        for (int c = 0; c < 4; c++) {
            uint32_t hi = f2tf(xs[c]);
            uint32_t lo = f2tf(xs[c] - __uint_as_float(hi));
            sAhi[row * SA_STRIDE + c4 + c] = hi;
            sAlo[row * SA_STRIDE + c4 + c] = lo;
        }
    }
    // ---- fill B tile (128 K x 64 cols of the fused [W1a|W1b]) ----
    for (int i = tid; i < HID * BLOCK_N; i += 256) {
        int k = i >> 6;
        int j = i & 63;
        int jg = by * BLOCK_N + j;
        float w = (jg < HID) ? W1[k * HID + jg]
                             : W1[(HID + k) * HID + (jg - HID)];
        uint32_t hi = f2tf(w);
        uint32_t lo = f2tf(w - __uint_as_float(hi));
        sBhi[k * SB_STRIDE + j] = hi;
        sBlo[k * SB_STRIDE + j] = lo;
    }
    __syncthreads();

    const int warp = tid >> 5, lane = tid & 31;
    const int wm = warp & 3;   // 0..3 -> 32-row slab
    const int wn = warp >> 2;  // 0..1 -> 32-col slab
    const int gid = lane >> 2, tig = lane & 3;

    float acc[2][4][4];
#pragma unroll
    for (int mi = 0; mi < 2; mi++)
#pragma unroll
        for (int ni = 0; ni < 4; ni++)
#pragma unroll
            for (int q = 0; q < 4; q++) acc[mi][ni][q] = 0.f;

#pragma unroll 4
    for (int k0 = 0; k0 < HID; k0 += 8) {
        uint32_t ahi[2][4], alo[2][4];
#pragma unroll
        for (int mi = 0; mi < 2; mi++) {
            int r = wm * 32 + mi * 16;
            int r0 = (r + gid) * SA_STRIDE;
            int r1 = (r + gid + 8) * SA_STRIDE;
            ahi[mi][0] = sAhi[r0 + k0 + tig];
            ahi[mi][1] = sAhi[r1 + k0 + tig];
            ahi[mi][2] = sAhi[r0 + k0 + tig + 4];
            ahi[mi][3] = sAhi[r1 + k0 + tig + 4];
            alo[mi][0] = sAlo[r0 + k0 + tig];
            alo[mi][1] = sAlo[r1 + k0 + tig];
            alo[mi][2] = sAlo[r0 + k0 + tig + 4];
            alo[mi][3] = sAlo[r1 + k0 + tig + 4];
        }
        uint32_t bhi[4][2], blo[4][2];
#pragma unroll
        for (int ni = 0; ni < 4; ni++) {
            int c = wn * 32 + ni * 8 + gid;
            bhi[ni][0] = sBhi[(k0 + tig) * SB_STRIDE + c];
            bhi[ni][1] = sBhi[(k0 + tig + 4) * SB_STRIDE + c];
            blo[ni][0] = sBlo[(k0 + tig) * SB_STRIDE + c];
            blo[ni][1] = sBlo[(k0 + tig + 4) * SB_STRIDE + c];
        }
#pragma unroll
        for (int mi = 0; mi < 2; mi++)
#pragma unroll
            for (int ni = 0; ni < 4; ni++) {
                mma_tf32(acc[mi][ni], ahi[mi], bhi[ni]);
                mma_tf32(acc[mi][ni], alo[mi], bhi[ni]);
                mma_tf32(acc[mi][ni], ahi[mi], blo[ni]);
            }
    }

    // ---- epilogue: add b1 for cols < 128, store float2 ----
#pragma unroll
    for (int mi = 0; mi < 2; mi++) {
#pragma unroll
        for (int ni = 0; ni < 4; ni++) {
            int col_local = wn * 32 + ni * 8 + 2 * tig;
            int gcol = by * BLOCK_N + col_local;
            float add0 = 0.f, add1 = 0.f;
            if (gcol < HID) {
                add0 = __ldg(b1 + gcol);
                add1 = __ldg(b1 + gcol + 1);
            }
            int row = m0 + wm * 32 + mi * 16 + gid;
            if (row < n_nodes) {
                float2 v = make_float2(acc[mi][ni][0] + add0, acc[mi][ni][1] + add1);
                *reinterpret_cast<float2*>(&g_table[(size_t)row * 256 + gcol]) = v;
            }
            int row2 = row + 8;
            if (row2 < n_nodes) {
                float2 v = make_float2(acc[mi][ni][2] + add0, acc[mi][ni][3] + add1);
                *reinterpret_cast<float2*>(&g_table[(size_t)row2 * 256 + gcol]) = v;
            }
        }
    }
}

// ---------------------------------------------------------------------------
// Detect index width: reference declares int64 but JAX w/o x64 emits int32.
// For int64 values < 2^31, every odd 32-bit word is 0; for random int32
// indices in [0,100000) the odds of 16 zeros in a row are ~0.
// ---------------------------------------------------------------------------
__global__ void detect_kernel(const uint32_t* __restrict__ s) {
    if (threadIdx.x == 0 && blockIdx.x == 0) {
        int is64 = 1;
        for (int i = 1; i < 32; i += 2)
            if (s[i] != 0u) { is64 = 0; break; }
        g_is64 = is64;
    }
}

// ---------------------------------------------------------------------------
// Edge kernel: warp per edge. lane loads float4 of T[s][0:128] and
// T[t][128:256] (coalesced 512B rows), relu+dot with W2, butterfly reduce.
// ---------------------------------------------------------------------------
__global__ void __launch_bounds__(256) edge_kernel(
    const void* __restrict__ srcv, const void* __restrict__ tgtv,
    const float* __restrict__ W2, const float* __restrict__ b2,
    float* __restrict__ out, int E)
{
    int gw = (int)((blockIdx.x * blockDim.x + threadIdx.x) >> 5);
    if (gw >= E) return;
    int lane = threadIdx.x & 31;

    long long s, t;
    if (g_is64) {
        s = reinterpret_cast<const long long*>(srcv)[gw];
        t = reinterpret_cast<const long long*>(tgtv)[gw];
    } else {
        s = reinterpret_cast<const int*>(srcv)[gw];
        t = reinterpret_cast<const int*>(tgtv)[gw];
    }

    const float4 a  = *reinterpret_cast<const float4*>(&g_table[(size_t)s * 256 + lane * 4]);
    const float4 bb = *reinterpret_cast<const float4*>(&g_table[(size_t)t * 256 + 128 + lane * 4]);
    const float4 w  = *reinterpret_cast<const float4*>(W2 + lane * 4);

    float sum = fmaxf(a.x + bb.x, 0.f) * w.x
              + fmaxf(a.y + bb.y, 0.f) * w.y
              + fmaxf(a.z + bb.z, 0.f) * w.z
              + fmaxf(a.w + bb.w, 0.f) * w.w;

#pragma unroll
    for (int off = 16; off; off >>= 1)
        sum += __shfl_xor_sync(0xFFFFFFFFu, sum, off);

    if (lane == 0) out[gw] = sum + __ldg(b2);
}

// ---------------------------------------------------------------------------
// launch
// ---------------------------------------------------------------------------
extern "C" void kernel_launch(void* const* d_in, const int* in_sizes, int n_in,
                              void* d_out, int out_size)
{
    const float* emb = (const float*)d_in[0];
    const void* src = d_in[1];
    const void* tgt = d_in[2];

    // edge_type_idx may or may not be materialized as an input; W1 has
    // 2*HID*HID = 32768 elements, which identifies it.
    int base = (n_in > 3 && in_sizes[3] == 2 * HID * HID) ? 3 : 4;
    const float* W1 = (const float*)d_in[base];
    const float* b1 = (const float*)d_in[base + 1];
    const float* W2 = (const float*)d_in[base + 2];
    const float* b2 = (const float*)d_in[base + 3];

    int n_nodes = in_sizes[0] / HID;
    int E = in_sizes[1];

    cudaFuncSetAttribute(precompute_kernel,
                         cudaFuncAttributeMaxDynamicSharedMemorySize, SMEM_BYTES);

    dim3 pgrid((n_nodes + BLOCK_M - 1) / BLOCK_M, 256 / BLOCK_N);
    precompute_kernel<<<pgrid, 256, SMEM_BYTES>>>(emb, W1, b1, n_nodes);

    detect_kernel<<<1, 32>>>((const uint32_t*)src);

    int nblocks = (E + 7) / 8;  // 8 warps (edges) per 256-thread block
    edge_kernel<<<nblocks, 256>>>(src, tgt, W2, b2, (float*)d_out, E);
}

// round 2
// speedup vs baseline: 1.6790x; 1.6790x over previous
#include <cuda_runtime.h>
#include <cuda_bf16.h>
#include <cstdint>
#include <cstddef>

#define HID 128
#define MAX_NODES 100096

// Precomputed table: row n = [emb[n]@W1[:128]+b1  |  emb[n]@W1[128:]]
__device__ float g_table[(size_t)MAX_NODES * 256];
__device__ int g_is64;

// ---------------------------------------------------------------------------
// helpers
// ---------------------------------------------------------------------------
__device__ __forceinline__ uint32_t pack_bf2(float x0, float x1) {
    __nv_bfloat162 p = __floats2bfloat162_rn(x0, x1);  // .x -> low half
    return *reinterpret_cast<uint32_t*>(&p);
}

__device__ __forceinline__ void mma_bf16(float* d, const uint32_t* a, const uint32_t* b) {
    asm volatile(
        "mma.sync.aligned.m16n8k16.row.col.f32.bf16.bf16.f32 "
        "{%0,%1,%2,%3}, {%4,%5,%6,%7}, {%8,%9}, {%0,%1,%2,%3};\n"
        : "+f"(d[0]), "+f"(d[1]), "+f"(d[2]), "+f"(d[3])
        : "r"(a[0]), "r"(a[1]), "r"(a[2]), "r"(a[3]), "r"(b[0]), "r"(b[1]));
}

// ---------------------------------------------------------------------------
// Precompute: T[n][256] = [emb@W1[:128]+b1 | emb@W1[128:]]
// bf16x3 split (hi/lo): acc += ah*bh + al*bh + ah*bl  (al*bl ~ 2^-16, dropped)
// Block tile: 128 (M) x 64 (N), K=128 resident. 8 warps = 4(M) x 2(N),
// warp tile 32x32 -> 2 m16-tiles x 4 n8-tiles, k-step 16.
// smem in b32 units (bf16 pairs), pitch 68 (64 data + 4 pad, conflict-free).
// ---------------------------------------------------------------------------
#define BLOCK_M 128
#define BLOCK_N 64
#define PITCH 68                       // b32 per row
#define SA_ELE (BLOCK_M * PITCH)       // 8704
#define SB_ELE (BLOCK_N * PITCH)       // 4352
#define SMEM_BYTES ((2 * SA_ELE + 2 * SB_ELE) * 4)   // 104448 B

__global__ void __launch_bounds__(256, 2) precompute_kernel(
    const float* __restrict__ emb, const float* __restrict__ W1,
    const float* __restrict__ b1, int n_nodes)
{
    extern __shared__ uint32_t sm[];
    uint32_t* sAhi = sm;
    uint32_t* sAlo = sm + SA_ELE;
    uint32_t* sBhi = sm + 2 * SA_ELE;
    uint32_t* sBlo = sm + 2 * SA_ELE + SB_ELE;

    const int tid = threadIdx.x;
    const int m0 = blockIdx.x * BLOCK_M;
    const int by = blockIdx.y;

    // ---- A tile: 128 rows x 128 K floats, hi/lo bf16 split ----
    for (int i = tid; i < BLOCK_M * (HID / 4); i += 256) {
        int row = i >> 5;            // 32 float4 per row
        int c4 = (i & 31) * 4;       // float column
        float4 v = make_float4(0.f, 0.f, 0.f, 0.f);
        if (m0 + row < n_nodes)
            v = *reinterpret_cast<const float4*>(emb + (size_t)(m0 + row) * HID + c4);
        float xs[4] = {v.x, v.y, v.z, v.w};
        float hi[4], lo[4];
#pragma unroll
        for (int c = 0; c < 4; c++) {
            __nv_bfloat16 h = __float2bfloat16_rn(xs[c]);
            hi[c] = __bfloat162float(h);
            lo[c] = xs[c] - hi[c];
        }
        int base = row * PITCH + c4 / 2;
        sAhi[base]     = pack_bf2(hi[0], hi[1]);
        sAhi[base + 1] = pack_bf2(hi[2], hi[3]);
        sAlo[base]     = pack_bf2(lo[0], lo[1]);
        sAlo[base + 1] = pack_bf2(lo[2], lo[3]);
    }
    // ---- B tile transposed: sB[n][k], n local 0..63, k 0..127 ----
    // n-fastest loop -> coalesced W1 loads (consecutive jg per thread).
    for (int i = tid; i < BLOCK_N * (HID / 2); i += 256) {
        int n = i & 63;
        int kb = i >> 6;             // b32 index -> k = 2*kb
        int k = kb * 2;
        int jg = by * BLOCK_N + n;
        float w0, w1;
        if (jg < HID) {
            w0 = W1[k * HID + jg];
            w1 = W1[(k + 1) * HID + jg];
        } else {
            w0 = W1[(HID + k) * HID + (jg - HID)];
            w1 = W1[(HID + k + 1) * HID + (jg - HID)];
        }
        __nv_bfloat16 h0 = __float2bfloat16_rn(w0);
        __nv_bfloat16 h1 = __float2bfloat16_rn(w1);
        float f0 = __bfloat162float(h0), f1 = __bfloat162float(h1);
        sBhi[n * PITCH + kb] = pack_bf2(f0, f1);
        sBlo[n * PITCH + kb] = pack_bf2(w0 - f0, w1 - f1);
    }
    __syncthreads();

    const int warp = tid >> 5, lane = tid & 31;
    const int wm = warp & 3;    // 4 M slabs of 32 rows
    const int wn = warp >> 2;   // 2 N slabs of 32 cols
    const int gid = lane >> 2, tig = lane & 3;

    float acc[2][4][4];
#pragma unroll
    for (int mi = 0; mi < 2; mi++)
#pragma unroll
        for (int ni = 0; ni < 4; ni++)
#pragma unroll
            for (int q = 0; q < 4; q++) acc[mi][ni][q] = 0.f;

#pragma unroll
    for (int ks = 0; ks < HID / 16; ks++) {
        const int kb0 = ks * 8;  // b32 offset of this k-step
        uint32_t ahi[2][4], alo[2][4];
#pragma unroll
        for (int mi = 0; mi < 2; mi++) {
            int r0 = (wm * 32 + mi * 16 + gid) * PITCH + kb0 + tig;
            int r1 = r0 + 8 * PITCH;
            ahi[mi][0] = sAhi[r0];     ahi[mi][1] = sAhi[r1];
            ahi[mi][2] = sAhi[r0 + 4]; ahi[mi][3] = sAhi[r1 + 4];
            alo[mi][0] = sAlo[r0];     alo[mi][1] = sAlo[r1];
            alo[mi][2] = sAlo[r0 + 4]; alo[mi][3] = sAlo[r1 + 4];
        }
        uint32_t bhi[4][2], blo[4][2];
#pragma unroll
        for (int ni = 0; ni < 4; ni++) {
            int c = (wn * 32 + ni * 8 + gid) * PITCH + kb0 + tig;
            bhi[ni][0] = sBhi[c]; bhi[ni][1] = sBhi[c + 4];
            blo[ni][0] = sBlo[c]; blo[ni][1] = sBlo[c + 4];
        }
        // pass-major order: dependent MMAs on one acc are 8 apart
#pragma unroll
        for (int mi = 0; mi < 2; mi++)
#pragma unroll
            for (int ni = 0; ni < 4; ni++)
                mma_bf16(acc[mi][ni], ahi[mi], bhi[ni]);
#pragma unroll
        for (int mi = 0; mi < 2; mi++)
#pragma unroll
            for (int ni = 0; ni < 4; ni++)
                mma_bf16(acc[mi][ni], alo[mi], bhi[ni]);
#pragma unroll
        for (int mi = 0; mi < 2; mi++)
#pragma unroll
            for (int ni = 0; ni < 4; ni++)
                mma_bf16(acc[mi][ni], ahi[mi], blo[ni]);
    }

    // ---- epilogue: +b1 for cols < 128, float2 stores ----
#pragma unroll
    for (int mi = 0; mi < 2; mi++) {
#pragma unroll
        for (int ni = 0; ni < 4; ni++) {
            int gcol = by * BLOCK_N + wn * 32 + ni * 8 + 2 * tig;
            float add0 = 0.f, add1 = 0.f;
            if (gcol < HID) {
                add0 = __ldg(b1 + gcol);
                add1 = __ldg(b1 + gcol + 1);
            }
            int row = m0 + wm * 32 + mi * 16 + gid;
            if (row < n_nodes) {
                float2 v = make_float2(acc[mi][ni][0] + add0, acc[mi][ni][1] + add1);
                *reinterpret_cast<float2*>(&g_table[(size_t)row * 256 + gcol]) = v;
            }
            if (row + 8 < n_nodes) {
                float2 v = make_float2(acc[mi][ni][2] + add0, acc[mi][ni][3] + add1);
                *reinterpret_cast<float2*>(&g_table[(size_t)(row + 8) * 256 + gcol]) = v;
            }
        }
    }
}

// ---------------------------------------------------------------------------
// Index width detection (int64 declared, but JAX w/o x64 emits int32).
// ---------------------------------------------------------------------------
__global__ void detect_kernel(const uint32_t* __restrict__ s) {
    if (threadIdx.x == 0 && blockIdx.x == 0) {
        int is64 = 1;
        for (int i = 1; i < 32; i += 2)
            if (s[i] != 0u) { is64 = 0; break; }
        g_is64 = is64;
    }
}

// ---------------------------------------------------------------------------
// Edge kernel: warp per TWO edges (4 independent 512B gathers in flight
// per thread). Lane loads float4 of T[s][0:128] and T[t][128:256],
// relu+dot with W2, butterfly reduce, lane0 writes.
// ---------------------------------------------------------------------------
__global__ void __launch_bounds__(256) edge_kernel(
    const void* __restrict__ srcv, const void* __restrict__ tgtv,
    const float* __restrict__ W2, const float* __restrict__ b2,
    float* __restrict__ out, int E)
{
    int gw = (int)((blockIdx.x * blockDim.x + threadIdx.x) >> 5);
    int e0 = gw * 2;
    if (e0 >= E) return;
    int lane = threadIdx.x & 31;
    int e1 = (e0 + 1 < E) ? e0 + 1 : e0;

    long long s0, t0, s1, t1;
    if (g_is64) {
        const long long* sp = (const long long*)srcv;
        const long long* tp = (const long long*)tgtv;
        s0 = sp[e0]; t0 = tp[e0]; s1 = sp[e1]; t1 = tp[e1];
    } else {
        const int* sp = (const int*)srcv;
        const int* tp = (const int*)tgtv;
        s0 = sp[e0]; t0 = tp[e0]; s1 = sp[e1]; t1 = tp[e1];
    }

    const float4 a0 = *reinterpret_cast<const float4*>(&g_table[(size_t)s0 * 256 + lane * 4]);
    const float4 c0 = *reinterpret_cast<const float4*>(&g_table[(size_t)t0 * 256 + 128 + lane * 4]);
    const float4 a1 = *reinterpret_cast<const float4*>(&g_table[(size_t)s1 * 256 + lane * 4]);
    const float4 c1 = *reinterpret_cast<const float4*>(&g_table[(size_t)t1 * 256 + 128 + lane * 4]);
    const float4 w  = *reinterpret_cast<const float4*>(W2 + lane * 4);

    float sum0 = fmaxf(a0.x + c0.x, 0.f) * w.x
               + fmaxf(a0.y + c0.y, 0.f) * w.y
               + fmaxf(a0.z + c0.z, 0.f) * w.z
               + fmaxf(a0.w + c0.w, 0.f) * w.w;
    float sum1 = fmaxf(a1.x + c1.x, 0.f) * w.x
               + fmaxf(a1.y + c1.y, 0.f) * w.y
               + fmaxf(a1.z + c1.z, 0.f) * w.z
               + fmaxf(a1.w + c1.w, 0.f) * w.w;

#pragma unroll
    for (int off = 16; off; off >>= 1) {
        sum0 += __shfl_xor_sync(0xFFFFFFFFu, sum0, off);
        sum1 += __shfl_xor_sync(0xFFFFFFFFu, sum1, off);
    }

    if (lane == 0) {
        float bias = __ldg(b2);
        out[e0] = sum0 + bias;
        if (e1 != e0) out[e1] = sum1 + bias;
    }
}

// ---------------------------------------------------------------------------
// launch
// ---------------------------------------------------------------------------
extern "C" void kernel_launch(void* const* d_in, const int* in_sizes, int n_in,
                              void* d_out, int out_size)
{
    const float* emb = (const float*)d_in[0];
    const void* src = d_in[1];
    const void* tgt = d_in[2];

    int base = (n_in > 3 && in_sizes[3] == 2 * HID * HID) ? 3 : 4;
    const float* W1 = (const float*)d_in[base];
    const float* b1 = (const float*)d_in[base + 1];
    const float* W2 = (const float*)d_in[base + 2];
    const float* b2 = (const float*)d_in[base + 3];

    int n_nodes = in_sizes[0] / HID;
    int E = in_sizes[1];

    cudaFuncSetAttribute(precompute_kernel,
                         cudaFuncAttributeMaxDynamicSharedMemorySize, SMEM_BYTES);

    dim3 pgrid((n_nodes + BLOCK_M - 1) / BLOCK_M, 256 / BLOCK_N);
    precompute_kernel<<<pgrid, 256, SMEM_BYTES>>>(emb, W1, b1, n_nodes);

    detect_kernel<<<1, 32>>>((const uint32_t*)src);

    // 8 warps/block, 2 edges/warp
    int warps_needed = (E + 1) / 2;
    int nblocks = (warps_needed + 7) / 8;
    edge_kernel<<<nblocks, 256>>>(src, tgt, W2, b2, (float*)d_out, E);
}

// round 4
// speedup vs baseline: 1.8948x; 1.1286x over previous
#include <cuda_runtime.h>
#include <cuda_fp16.h>
#include <cuda_bf16.h>
#include <cstdint>
#include <cstddef>

#define HID 128
#define MAX_NODES 100096

// fp16 table: row n = [fp16(emb[n]@W1[:128]+b1) | fp16(emb[n]@W1[128:])]
__device__ __half g_table[(size_t)MAX_NODES * 256];
__device__ int g_is64;

// ---------------------------------------------------------------------------
// helpers
// ---------------------------------------------------------------------------
__device__ __forceinline__ uint32_t smem_u32(const void* p) {
    uint32_t a;
    asm("{ .reg .u64 t; cvta.to.shared.u64 t, %1; cvt.u32.u64 %0, t; }" : "=r"(a) : "l"(p));
    return a;
}

__device__ __forceinline__ uint32_t pack_bf2(float x0, float x1) {
    __nv_bfloat162 p = __floats2bfloat162_rn(x0, x1);  // .x -> low half
    return *reinterpret_cast<uint32_t*>(&p);
}

__device__ __forceinline__ void mma_bf16(float* d, const uint32_t* a, const uint32_t* b) {
    asm volatile(
        "mma.sync.aligned.m16n8k16.row.col.f32.bf16.bf16.f32 "
        "{%0,%1,%2,%3}, {%4,%5,%6,%7}, {%8,%9}, {%0,%1,%2,%3};\n"
        : "+f"(d[0]), "+f"(d[1]), "+f"(d[2]), "+f"(d[3])
        : "r"(a[0]), "r"(a[1]), "r"(a[2]), "r"(a[3]), "r"(b[0]), "r"(b[1]));
}

__device__ __forceinline__ void ldsm_x4(uint32_t* r, uint32_t addr) {
    asm volatile("ldmatrix.sync.aligned.m8n8.x4.shared.b16 {%0,%1,%2,%3}, [%4];"
                 : "=r"(r[0]), "=r"(r[1]), "=r"(r[2]), "=r"(r[3]) : "r"(addr));
}

// ---------------------------------------------------------------------------
// Precompute: T[n][256] = fp16([emb@W1[:128]+b1 | emb@W1[128:]])
// bf16x3 split: acc += ah*bh + al*bh + ah*bl (fp32 accum).
// Block tile 128(M) x 64(N), K=128 resident, 8 warps = 4(M) x 2(N),
// warp tile 32x32. All fragment loads via ldmatrix.x4.
// smem pitch 68 b32 (64 data + 4 pad): ldmatrix row stride 272 B -> bank
// phase 4r mod 32, conflict-free.
// ---------------------------------------------------------------------------
#define BLOCK_M 128
#define BLOCK_N 64
#define PITCH 68
#define SA_ELE (BLOCK_M * PITCH)       // 8704 b32
#define SB_ELE (BLOCK_N * PITCH)       // 4352 b32
#define SMEM_BYTES ((2 * SA_ELE + 2 * SB_ELE) * 4)   // 104448 B

__global__ void __launch_bounds__(256, 2) precompute_kernel(
    const float* __restrict__ emb, const float* __restrict__ W1,
    const float* __restrict__ b1, int n_nodes)
{
    extern __shared__ uint32_t sm[];
    uint32_t* sAhi = sm;
    uint32_t* sAlo = sm + SA_ELE;
    uint32_t* sBhi = sm + 2 * SA_ELE;
    uint32_t* sBlo = sm + 2 * SA_ELE + SB_ELE;

    const int tid = threadIdx.x;
    const int m0 = blockIdx.x * BLOCK_M;
    const int by = blockIdx.y;

    // ---- A tile: 128 rows x 128 K floats, hi/lo bf16 split ----
    for (int i = tid; i < BLOCK_M * (HID / 4); i += 256) {
        int row = i >> 5;
        int c4 = (i & 31) * 4;
        float4 v = make_float4(0.f, 0.f, 0.f, 0.f);
        if (m0 + row < n_nodes)
            v = *reinterpret_cast<const float4*>(emb + (size_t)(m0 + row) * HID + c4);
        float xs[4] = {v.x, v.y, v.z, v.w};
        float hi[4], lo[4];
#pragma unroll
        for (int c = 0; c < 4; c++) {
            __nv_bfloat16 h = __float2bfloat16_rn(xs[c]);
            hi[c] = __bfloat162float(h);
            lo[c] = xs[c] - hi[c];
        }
        int base = row * PITCH + c4 / 2;
        sAhi[base]     = pack_bf2(hi[0], hi[1]);
        sAhi[base + 1] = pack_bf2(hi[2], hi[3]);
        sAlo[base]     = pack_bf2(lo[0], lo[1]);
        sAlo[base + 1] = pack_bf2(lo[2], lo[3]);
    }
    // ---- B tile transposed: sB[n][k] (n local 0..63), coalesced W1 reads ----
    for (int i = tid; i < BLOCK_N * (HID / 2); i += 256) {
        int n = i & 63;
        int kb = i >> 6;
        int k = kb * 2;
        int jg = by * BLOCK_N + n;
        float w0, w1;
        if (jg < HID) {
            w0 = W1[k * HID + jg];
            w1 = W1[(k + 1) * HID + jg];
        } else {
            w0 = W1[(HID + k) * HID + (jg - HID)];
            w1 = W1[(HID + k + 1) * HID + (jg - HID)];
        }
        __nv_bfloat16 h0 = __float2bfloat16_rn(w0);
        __nv_bfloat16 h1 = __float2bfloat16_rn(w1);
        float f0 = __bfloat162float(h0), f1 = __bfloat162float(h1);
        sBhi[n * PITCH + kb] = pack_bf2(f0, f1);
        sBlo[n * PITCH + kb] = pack_bf2(w0 - f0, w1 - f1);
    }
    __syncthreads();

    const int warp = tid >> 5, lane = tid & 31;
    const int wm = warp & 3;    // 4 M slabs of 32 rows
    const int wn = warp >> 2;   // 2 N slabs of 32 cols
    const int gid = lane >> 2, tig = lane & 3;

    // ldmatrix per-lane address components (b32 units -> bytes at use site)
    // A x4 (16x16): lanes 0-15 rows, 16-31 rows w/ +4 b32 chunk
    const int a_row = (lane & 15);
    const int a_kb  = (lane >> 4) * 4;
    // B x4 (two 8-row n-tiles x k16): lanes 0-7 n0 k0, 8-15 n0 k+4, 16-23 n0+8 k0, 24-31 n0+8 k+4
    const int b_n  = (lane & 7) + (lane >> 4) * 8;
    const int b_kb = ((lane >> 3) & 1) * 4;

    const uint32_t sAhi_a = smem_u32(sAhi), sAlo_a = smem_u32(sAlo);
    const uint32_t sBhi_a = smem_u32(sBhi), sBlo_a = smem_u32(sBlo);

    float acc[2][4][4];
#pragma unroll
    for (int mi = 0; mi < 2; mi++)
#pragma unroll
        for (int ni = 0; ni < 4; ni++)
#pragma unroll
            for (int q = 0; q < 4; q++) acc[mi][ni][q] = 0.f;

#pragma unroll
    for (int ks = 0; ks < HID / 16; ks++) {
        const int kb0 = ks * 8;
        uint32_t ahi[2][4], alo[2][4], bhi[2][4], blo[2][4];
#pragma unroll
        for (int mi = 0; mi < 2; mi++) {
            uint32_t off = ((wm * 32 + mi * 16 + a_row) * PITCH + kb0 + a_kb) * 4u;
            ldsm_x4(ahi[mi], sAhi_a + off);
            ldsm_x4(alo[mi], sAlo_a + off);
        }
#pragma unroll
        for (int pr = 0; pr < 2; pr++) {   // pr covers n-tiles {2pr, 2pr+1}
            uint32_t off = ((wn * 32 + pr * 16 + b_n) * PITCH + kb0 + b_kb) * 4u;
            ldsm_x4(bhi[pr], sBhi_a + off);
            ldsm_x4(blo[pr], sBlo_a + off);
        }
        // pass-major: 8 independent MMAs between same-acc reuse
#pragma unroll
        for (int mi = 0; mi < 2; mi++)
#pragma unroll
            for (int ni = 0; ni < 4; ni++)
                mma_bf16(acc[mi][ni], ahi[mi], &bhi[ni >> 1][(ni & 1) * 2]);
#pragma unroll
        for (int mi = 0; mi < 2; mi++)
#pragma unroll
            for (int ni = 0; ni < 4; ni++)
                mma_bf16(acc[mi][ni], alo[mi], &bhi[ni >> 1][(ni & 1) * 2]);
#pragma unroll
        for (int mi = 0; mi < 2; mi++)
#pragma unroll
            for (int ni = 0; ni < 4; ni++)
                mma_bf16(acc[mi][ni], ahi[mi], &blo[ni >> 1][(ni & 1) * 2]);
    }

    // ---- epilogue: +b1 for cols < 128, pack fp16, 4B stores ----
#pragma unroll
    for (int mi = 0; mi < 2; mi++) {
#pragma unroll
        for (int ni = 0; ni < 4; ni++) {
            int gcol = by * BLOCK_N + wn * 32 + ni * 8 + 2 * tig;
            float add0 = 0.f, add1 = 0.f;
            if (gcol < HID) {
                add0 = __ldg(b1 + gcol);
                add1 = __ldg(b1 + gcol + 1);
            }
            int row = m0 + wm * 32 + mi * 16 + gid;
            if (row < n_nodes) {
                __half2 h = __floats2half2_rn(acc[mi][ni][0] + add0, acc[mi][ni][1] + add1);
                *reinterpret_cast<__half2*>(&g_table[(size_t)row * 256 + gcol]) = h;
            }
            if (row + 8 < n_nodes) {
                __half2 h = __floats2half2_rn(acc[mi][ni][2] + add0, acc[mi][ni][3] + add1);
                *reinterpret_cast<__half2*>(&g_table[(size_t)(row + 8) * 256 + gcol]) = h;
            }
        }
    }
}

// ---------------------------------------------------------------------------
// Index width detection (int64 declared, but JAX w/o x64 emits int32).
// ---------------------------------------------------------------------------
__global__ void detect_kernel(const uint32_t* __restrict__ s) {
    if (threadIdx.x == 0 && blockIdx.x == 0) {
        int is64 = 1;
        for (int i = 1; i < 32; i += 2)
            if (s[i] != 0u) { is64 = 0; break; }
        g_is64 = is64;
    }
}

// ---------------------------------------------------------------------------
// Edge kernel: warp per TWO edges; fp16 table -> 256 B per gather
// (uint2 = 4 halves per lane). relu+dot in fp32, butterfly reduce.
// ---------------------------------------------------------------------------
__device__ __forceinline__ float dot4_relu(uint2 a, uint2 c, float4 w) {
    float2 a0 = __half22float2(*reinterpret_cast<__half2*>(&a.x));
    float2 a1 = __half22float2(*reinterpret_cast<__half2*>(&a.y));
    float2 c0 = __half22float2(*reinterpret_cast<__half2*>(&c.x));
    float2 c1 = __half22float2(*reinterpret_cast<__half2*>(&c.y));
    return fmaxf(a0.x + c0.x, 0.f) * w.x + fmaxf(a0.y + c0.y, 0.f) * w.y
         + fmaxf(a1.x + c1.x, 0.f) * w.z + fmaxf(a1.y + c1.y, 0.f) * w.w;
}

__global__ void __launch_bounds__(256) edge_kernel(
    const void* __restrict__ srcv, const void* __restrict__ tgtv,
    const float* __restrict__ W2, const float* __restrict__ b2,
    float* __restrict__ out, int E)
{
    int gw = (int)((blockIdx.x * blockDim.x + threadIdx.x) >> 5);
    int e0 = gw * 2;
    if (e0 >= E) return;
    int lane = threadIdx.x & 31;
    int e1 = (e0 + 1 < E) ? e0 + 1 : e0;

    long long s0, t0, s1, t1;
    if (g_is64) {
        const long long* sp = (const long long*)srcv;
        const long long* tp = (const long long*)tgtv;
        s0 = sp[e0]; t0 = tp[e0]; s1 = sp[e1]; t1 = tp[e1];
    } else {
        const int* sp = (const int*)srcv;
        const int* tp = (const int*)tgtv;
        s0 = sp[e0]; t0 = tp[e0]; s1 = sp[e1]; t1 = tp[e1];
    }

    const uint2 a0 = *reinterpret_cast<const uint2*>(&g_table[(size_t)s0 * 256 + lane * 4]);
    const uint2 c0 = *reinterpret_cast<const uint2*>(&g_table[(size_t)t0 * 256 + 128 + lane * 4]);
    const uint2 a1 = *reinterpret_cast<const uint2*>(&g_table[(size_t)s1 * 256 + lane * 4]);
    const uint2 c1 = *reinterpret_cast<const uint2*>(&g_table[(size_t)t1 * 256 + 128 + lane * 4]);
    const float4 w = *reinterpret_cast<const float4*>(W2 + lane * 4);

    float sum0 = dot4_relu(a0, c0, w);
    float sum1 = dot4_relu(a1, c1, w);

#pragma unroll
    for (int off = 16; off; off >>= 1) {
        sum0 += __shfl_xor_sync(0xFFFFFFFFu, sum0, off);
        sum1 += __shfl_xor_sync(0xFFFFFFFFu, sum1, off);
    }

    if (lane == 0) {
        float bias = __ldg(b2);
        out[e0] = sum0 + bias;
        if (e1 != e0) out[e1] = sum1 + bias;
    }
}

// ---------------------------------------------------------------------------
// launch
// ---------------------------------------------------------------------------
extern "C" void kernel_launch(void* const* d_in, const int* in_sizes, int n_in,
                              void* d_out, int out_size)
{
    const float* emb = (const float*)d_in[0];
    const void* src = d_in[1];
    const void* tgt = d_in[2];

    int base = (n_in > 3 && in_sizes[3] == 2 * HID * HID) ? 3 : 4;
    const float* W1 = (const float*)d_in[base];
    const float* b1 = (const float*)d_in[base + 1];
    const float* W2 = (const float*)d_in[base + 2];
    const float* b2 = (const float*)d_in[base + 3];

    int n_nodes = in_sizes[0] / HID;
    int E = in_sizes[1];

    cudaFuncSetAttribute(precompute_kernel,
                         cudaFuncAttributeMaxDynamicSharedMemorySize, SMEM_BYTES);

    dim3 pgrid((n_nodes + BLOCK_M - 1) / BLOCK_M, 256 / BLOCK_N);
    precompute_kernel<<<pgrid, 256, SMEM_BYTES>>>(emb, W1, b1, n_nodes);

    detect_kernel<<<1, 32>>>((const uint32_t*)src);

    int warps_needed = (E + 1) / 2;
    int nblocks = (warps_needed + 7) / 8;
    edge_kernel<<<nblocks, 256>>>(src, tgt, W2, b2, (float*)d_out, E);
}

// round 5
// speedup vs baseline: 2.9121x; 1.5369x over previous
#include <cuda_runtime.h>
#include <cuda_fp16.h>
#include <cuda_bf16.h>
#include <cstdint>
#include <cstddef>

#define HID 128
#define MAX_NODES 100096

// fp16 table: row n = [fp16(emb[n]@W1[:128]+b1) | fp16(emb[n]@W1[128:])]
__device__ __half g_table[(size_t)MAX_NODES * 256];
__device__ int g_is64;

#define PITCH 68
#define SB_ELE (64 * PITCH)            // 4352 b32 per 64-col N-tile
// staged W1 hi/lo in the exact padded smem layout, 4 N-tiles
__device__ uint32_t g_sBhi[4 * SB_ELE];
__device__ uint32_t g_sBlo[4 * SB_ELE];

// ---------------------------------------------------------------------------
// helpers
// ---------------------------------------------------------------------------
__device__ __forceinline__ uint32_t smem_u32(const void* p) {
    uint32_t a;
    asm("{ .reg .u64 t; cvta.to.shared.u64 t, %1; cvt.u32.u64 %0, t; }" : "=r"(a) : "l"(p));
    return a;
}

__device__ __forceinline__ uint32_t pack_bf2(float x0, float x1) {
    __nv_bfloat162 p = __floats2bfloat162_rn(x0, x1);  // .x -> low half
    return *reinterpret_cast<uint32_t*>(&p);
}

__device__ __forceinline__ void mma_bf16(float* d, const uint32_t* a, const uint32_t* b) {
    asm volatile(
        "mma.sync.aligned.m16n8k16.row.col.f32.bf16.bf16.f32 "
        "{%0,%1,%2,%3}, {%4,%5,%6,%7}, {%8,%9}, {%0,%1,%2,%3};\n"
        : "+f"(d[0]), "+f"(d[1]), "+f"(d[2]), "+f"(d[3])
        : "r"(a[0]), "r"(a[1]), "r"(a[2]), "r"(a[3]), "r"(b[0]), "r"(b[1]));
}

__device__ __forceinline__ void ldsm_x4(uint32_t* r, uint32_t addr) {
    asm volatile("ldmatrix.sync.aligned.m8n8.x4.shared.b16 {%0,%1,%2,%3}, [%4];"
                 : "=r"(r[0]), "=r"(r[1]), "=r"(r[2]), "=r"(r[3]) : "r"(addr));
}

// ---------------------------------------------------------------------------
// Prep: split fused W [256(N) x 128(K)] into bf16 hi/lo in the padded
// [n_local][kb] layout (pitch 68 b32), 4 tiles of 64 N each.
// ---------------------------------------------------------------------------
__global__ void prep_w1_kernel(const float* __restrict__ W1) {
    int i = blockIdx.x * blockDim.x + threadIdx.x;  // 0..16383
    if (i >= 256 * 64) return;
    int n = i & 255;             // fused output column
    int kb = i >> 8;             // b32 index along K (k = 2*kb)
    int k = kb * 2;
    float w0, w1;
    if (n < HID) {
        w0 = W1[k * HID + n];
        w1 = W1[(k + 1) * HID + n];
    } else {
        w0 = W1[(HID + k) * HID + (n - HID)];
        w1 = W1[(HID + k + 1) * HID + (n - HID)];
    }
    __nv_bfloat16 h0 = __float2bfloat16_rn(w0);
    __nv_bfloat16 h1 = __float2bfloat16_rn(w1);
    float f0 = __bfloat162float(h0), f1 = __bfloat162float(h1);
    int idx = (n >> 6) * SB_ELE + (n & 63) * PITCH + kb;
    g_sBhi[idx] = pack_bf2(f0, f1);
    g_sBlo[idx] = pack_bf2(w0 - f0, w1 - f1);
}

// ---------------------------------------------------------------------------
// Precompute: T[n][256] = fp16([emb@W1[:128]+b1 | emb@W1[128:]])
// bf16x3: acc += ah*bh + al*bh + ah*bl (fp32 accum).
// A (128 rows x K=128) loaded/split ONCE per CTA; loop 4 N-tiles of 64,
// B tiles block-copied from the pre-split staging arrays.
// 8 warps = 4(M) x 2(N), warp tile 32x32. ldmatrix.x4 fragment loads.
// ---------------------------------------------------------------------------
#define BLOCK_M 128
#define SA_ELE (BLOCK_M * PITCH)       // 8704 b32
#define SMEM_BYTES ((2 * SA_ELE + 2 * SB_ELE) * 4)   // 104448 B

__global__ void __launch_bounds__(256, 2) precompute_kernel(
    const float* __restrict__ emb, const float* __restrict__ b1, int n_nodes)
{
    extern __shared__ uint32_t sm[];
    uint32_t* sAhi = sm;
    uint32_t* sAlo = sm + SA_ELE;
    uint32_t* sBhi = sm + 2 * SA_ELE;
    uint32_t* sBlo = sm + 2 * SA_ELE + SB_ELE;

    const int tid = threadIdx.x;
    const int m0 = blockIdx.x * BLOCK_M;

    // ---- A tile: 128 rows x 128 K floats, hi/lo bf16 split (once) ----
    for (int i = tid; i < BLOCK_M * (HID / 4); i += 256) {
        int row = i >> 5;
        int c4 = (i & 31) * 4;
        float4 v = make_float4(0.f, 0.f, 0.f, 0.f);
        if (m0 + row < n_nodes)
            v = *reinterpret_cast<const float4*>(emb + (size_t)(m0 + row) * HID + c4);
        float xs[4] = {v.x, v.y, v.z, v.w};
        float hi[4], lo[4];
#pragma unroll
        for (int c = 0; c < 4; c++) {
            __nv_bfloat16 h = __float2bfloat16_rn(xs[c]);
            hi[c] = __bfloat162float(h);
            lo[c] = xs[c] - hi[c];
        }
        int base = row * PITCH + c4 / 2;
        sAhi[base]     = pack_bf2(hi[0], hi[1]);
        sAhi[base + 1] = pack_bf2(hi[2], hi[3]);
        sAlo[base]     = pack_bf2(lo[0], lo[1]);
        sAlo[base + 1] = pack_bf2(lo[2], lo[3]);
    }

    const int warp = tid >> 5, lane = tid & 31;
    const int wm = warp & 3;    // 4 M slabs of 32 rows
    const int wn = warp >> 2;   // 2 N slabs of 32 cols
    const int gid = lane >> 2, tig = lane & 3;

    const int a_row = (lane & 15);
    const int a_kb  = (lane >> 4) * 4;
    const int b_n  = (lane & 7) + (lane >> 4) * 8;
    const int b_kb = ((lane >> 3) & 1) * 4;

    const uint32_t sAhi_a = smem_u32(sAhi), sAlo_a = smem_u32(sAlo);
    const uint32_t sBhi_a = smem_u32(sBhi), sBlo_a = smem_u32(sBlo);

    for (int nt = 0; nt < 4; nt++) {
        // ---- copy pre-split B tile (pure uint4 copies from L2) ----
        {
            const uint4* shi = reinterpret_cast<const uint4*>(g_sBhi + nt * SB_ELE);
            const uint4* slo = reinterpret_cast<const uint4*>(g_sBlo + nt * SB_ELE);
            uint4* dhi = reinterpret_cast<uint4*>(sBhi);
            uint4* dlo = reinterpret_cast<uint4*>(sBlo);
            for (int i = tid; i < SB_ELE / 4; i += 256) {
                dhi[i] = shi[i];
                dlo[i] = slo[i];
            }
        }
        __syncthreads();

        float acc[2][4][4];
#pragma unroll
        for (int mi = 0; mi < 2; mi++)
#pragma unroll
            for (int ni = 0; ni < 4; ni++)
#pragma unroll
                for (int q = 0; q < 4; q++) acc[mi][ni][q] = 0.f;

#pragma unroll
        for (int ks = 0; ks < HID / 16; ks++) {
            const int kb0 = ks * 8;
            uint32_t ahi[2][4], alo[2][4], bhi[2][4], blo[2][4];
#pragma unroll
            for (int mi = 0; mi < 2; mi++) {
                uint32_t off = ((wm * 32 + mi * 16 + a_row) * PITCH + kb0 + a_kb) * 4u;
                ldsm_x4(ahi[mi], sAhi_a + off);
                ldsm_x4(alo[mi], sAlo_a + off);
            }
#pragma unroll
            for (int pr = 0; pr < 2; pr++) {
                uint32_t off = ((wn * 32 + pr * 16 + b_n) * PITCH + kb0 + b_kb) * 4u;
                ldsm_x4(bhi[pr], sBhi_a + off);
                ldsm_x4(blo[pr], sBlo_a + off);
            }
#pragma unroll
            for (int mi = 0; mi < 2; mi++)
#pragma unroll
                for (int ni = 0; ni < 4; ni++)
                    mma_bf16(acc[mi][ni], ahi[mi], &bhi[ni >> 1][(ni & 1) * 2]);
#pragma unroll
            for (int mi = 0; mi < 2; mi++)
#pragma unroll
                for (int ni = 0; ni < 4; ni++)
                    mma_bf16(acc[mi][ni], alo[mi], &bhi[ni >> 1][(ni & 1) * 2]);
#pragma unroll
            for (int mi = 0; mi < 2; mi++)
#pragma unroll
                for (int ni = 0; ni < 4; ni++)
                    mma_bf16(acc[mi][ni], ahi[mi], &blo[ni >> 1][(ni & 1) * 2]);
        }

        // ---- epilogue: +b1 for cols < 128, fp16 pack, 4B stores ----
#pragma unroll
        for (int mi = 0; mi < 2; mi++) {
#pragma unroll
            for (int ni = 0; ni < 4; ni++) {
                int gcol = nt * 64 + wn * 32 + ni * 8 + 2 * tig;
                float add0 = 0.f, add1 = 0.f;
                if (gcol < HID) {
                    add0 = __ldg(b1 + gcol);
                    add1 = __ldg(b1 + gcol + 1);
                }
                int row = m0 + wm * 32 + mi * 16 + gid;
                if (row < n_nodes) {
                    __half2 h = __floats2half2_rn(acc[mi][ni][0] + add0, acc[mi][ni][1] + add1);
                    *reinterpret_cast<__half2*>(&g_table[(size_t)row * 256 + gcol]) = h;
                }
                if (row + 8 < n_nodes) {
                    __half2 h = __floats2half2_rn(acc[mi][ni][2] + add0, acc[mi][ni][3] + add1);
                    *reinterpret_cast<__half2*>(&g_table[(size_t)(row + 8) * 256 + gcol]) = h;
                }
            }
        }
        __syncthreads();   // all MMA reads of B done before next tile's copy
    }
}

// ---------------------------------------------------------------------------
// Index width detection (int64 declared, but JAX w/o x64 emits int32).
// ---------------------------------------------------------------------------
__global__ void detect_kernel(const uint32_t* __restrict__ s) {
    if (threadIdx.x == 0 && blockIdx.x == 0) {
        int is64 = 1;
        for (int i = 1; i < 32; i += 2)
            if (s[i] != 0u) { is64 = 0; break; }
        g_is64 = is64;
    }
}

// ---------------------------------------------------------------------------
// Edge kernel: half-warp (16 lanes) per edge, 4 edges per warp.
// Lane loads uint4 (8 halves = 16B); 16 lanes cover a 256B table row part.
// 4 independent gathers in flight per thread (64B MLP).
// ---------------------------------------------------------------------------
__device__ __forceinline__ float dot8_relu(uint4 a, uint4 c, float4 w0, float4 w1) {
    float2 a0 = __half22float2(*reinterpret_cast<__half2*>(&a.x));
    float2 a1 = __half22float2(*reinterpret_cast<__half2*>(&a.y));
    float2 a2 = __half22float2(*reinterpret_cast<__half2*>(&a.z));
    float2 a3 = __half22float2(*reinterpret_cast<__half2*>(&a.w));
    float2 c0 = __half22float2(*reinterpret_cast<__half2*>(&c.x));
    float2 c1 = __half22float2(*reinterpret_cast<__half2*>(&c.y));
    float2 c2 = __half22float2(*reinterpret_cast<__half2*>(&c.z));
    float2 c3 = __half22float2(*reinterpret_cast<__half2*>(&c.w));
    float s = fmaxf(a0.x + c0.x, 0.f) * w0.x + fmaxf(a0.y + c0.y, 0.f) * w0.y
            + fmaxf(a1.x + c1.x, 0.f) * w0.z + fmaxf(a1.y + c1.y, 0.f) * w0.w;
    s += fmaxf(a2.x + c2.x, 0.f) * w1.x + fmaxf(a2.y + c2.y, 0.f) * w1.y
       + fmaxf(a3.x + c3.x, 0.f) * w1.z + fmaxf(a3.y + c3.y, 0.f) * w1.w;
    return s;
}

__global__ void __launch_bounds__(256) edge_kernel(
    const void* __restrict__ srcv, const void* __restrict__ tgtv,
    const float* __restrict__ W2, const float* __restrict__ b2,
    float* __restrict__ out, int E)
{
    int gw = (int)((blockIdx.x * blockDim.x + threadIdx.x) >> 5);
    int base = gw * 4;
    if (base >= E) return;
    int lane = threadIdx.x & 31;
    int half = lane >> 4, l16 = lane & 15;

    int ea = base + half * 2;
    int eb = ea + 1;
    bool va = ea < E, vb = eb < E;
    int la = va ? ea : 0;
    int lb = vb ? eb : 0;

    long long sa, ta, sb, tb;
    if (g_is64) {
        const long long* sp = (const long long*)srcv;
        const long long* tp = (const long long*)tgtv;
        sa = sp[la]; ta = tp[la]; sb = sp[lb]; tb = tp[lb];
    } else {
        const int* sp = (const int*)srcv;
        const int* tp = (const int*)tgtv;
        sa = sp[la]; ta = tp[la]; sb = sp[lb]; tb = tp[lb];
    }

    const uint4 Aa = *reinterpret_cast<const uint4*>(&g_table[(size_t)sa * 256 + l16 * 8]);
    const uint4 Ca = *reinterpret_cast<const uint4*>(&g_table[(size_t)ta * 256 + 128 + l16 * 8]);
    const uint4 Ab = *reinterpret_cast<const uint4*>(&g_table[(size_t)sb * 256 + l16 * 8]);
    const uint4 Cb = *reinterpret_cast<const uint4*>(&g_table[(size_t)tb * 256 + 128 + l16 * 8]);
    const float4 w0 = *reinterpret_cast<const float4*>(W2 + l16 * 8);
    const float4 w1 = *reinterpret_cast<const float4*>(W2 + l16 * 8 + 4);

    float suma = dot8_relu(Aa, Ca, w0, w1);
    float sumb = dot8_relu(Ab, Cb, w0, w1);

#pragma unroll
    for (int off = 8; off; off >>= 1) {
        suma += __shfl_xor_sync(0xFFFFFFFFu, suma, off);
        sumb += __shfl_xor_sync(0xFFFFFFFFu, sumb, off);
    }

    if (l16 == 0) {
        float bias = __ldg(b2);
        if (va) out[ea] = suma + bias;
        if (vb) out[eb] = sumb + bias;
    }
}

// ---------------------------------------------------------------------------
// launch
// ---------------------------------------------------------------------------
extern "C" void kernel_launch(void* const* d_in, const int* in_sizes, int n_in,
                              void* d_out, int out_size)
{
    const float* emb = (const float*)d_in[0];
    const void* src = d_in[1];
    const void* tgt = d_in[2];

    int base = (n_in > 3 && in_sizes[3] == 2 * HID * HID) ? 3 : 4;
    const float* W1 = (const float*)d_in[base];
    const float* b1 = (const float*)d_in[base + 1];
    const float* W2 = (const float*)d_in[base + 2];
    const float* b2 = (const float*)d_in[base + 3];

    int n_nodes = in_sizes[0] / HID;
    int E = in_sizes[1];

    prep_w1_kernel<<<64, 256>>>(W1);

    cudaFuncSetAttribute(precompute_kernel,
                         cudaFuncAttributeMaxDynamicSharedMemorySize, SMEM_BYTES);
    int pgrid = (n_nodes + BLOCK_M - 1) / BLOCK_M;
    precompute_kernel<<<pgrid, 256, SMEM_BYTES>>>(emb, b1, n_nodes);

    detect_kernel<<<1, 32>>>((const uint32_t*)src);

    // 8 warps/block, 4 edges/warp
    int warps_needed = (E + 3) / 4;
    int nblocks = (warps_needed + 7) / 8;
    edge_kernel<<<nblocks, 256>>>(src, tgt, W2, b2, (float*)d_out, E);
}

// round 6
// speedup vs baseline: 3.7954x; 1.3033x over previous
#include <cuda_runtime.h>
#include <cuda_fp16.h>
#include <cuda_bf16.h>
#include <cstdint>
#include <cstddef>

#define HID 128
#define MAX_NODES 100096

// fp16 table: row n = [fp16(emb[n]@W1[:128]+b1) | fp16(emb[n]@W1[128:])]
__device__ __half g_table[(size_t)MAX_NODES * 256];
__device__ int g_is64;

#define PITCH 68
#define SB_ELE (64 * PITCH)            // 4352 b32 per 64-col N-tile
// staged fp16 W1 in the exact padded smem layout, 4 N-tiles of 64
__device__ uint32_t g_sB[4 * SB_ELE];

// ---------------------------------------------------------------------------
// helpers
// ---------------------------------------------------------------------------
__device__ __forceinline__ uint32_t smem_u32(const void* p) {
    uint32_t a;
    asm("{ .reg .u64 t; cvta.to.shared.u64 t, %1; cvt.u32.u64 %0, t; }" : "=r"(a) : "l"(p));
    return a;
}

__device__ __forceinline__ uint32_t pack_h2(float x0, float x1) {
    __half2 p = __floats2half2_rn(x0, x1);  // .x -> low half
    return *reinterpret_cast<uint32_t*>(&p);
}

__device__ __forceinline__ void mma_f16(float* d, const uint32_t* a, const uint32_t* b) {
    asm volatile(
        "mma.sync.aligned.m16n8k16.row.col.f32.f16.f16.f32 "
        "{%0,%1,%2,%3}, {%4,%5,%6,%7}, {%8,%9}, {%0,%1,%2,%3};\n"
        : "+f"(d[0]), "+f"(d[1]), "+f"(d[2]), "+f"(d[3])
        : "r"(a[0]), "r"(a[1]), "r"(a[2]), "r"(a[3]), "r"(b[0]), "r"(b[1]));
}

__device__ __forceinline__ void ldsm_x4(uint32_t* r, uint32_t addr) {
    asm volatile("ldmatrix.sync.aligned.m8n8.x4.shared.b16 {%0,%1,%2,%3}, [%4];"
                 : "=r"(r[0]), "=r"(r[1]), "=r"(r[2]), "=r"(r[3]) : "r"(addr));
}

// ---------------------------------------------------------------------------
// Prep: fused W [256(N) x 128(K)] -> fp16 pairs in the padded [n][kb]
// layout (pitch 68 b32), 4 tiles of 64 N each.
// ---------------------------------------------------------------------------
__global__ void prep_w1_kernel(const float* __restrict__ W1) {
    int i = blockIdx.x * blockDim.x + threadIdx.x;  // 0..16383
    if (i >= 256 * 64) return;
    int n = i & 255;
    int kb = i >> 8;             // b32 index along K (k = 2*kb)
    int k = kb * 2;
    float w0, w1;
    if (n < HID) {
        w0 = W1[k * HID + n];
        w1 = W1[(k + 1) * HID + n];
    } else {
        w0 = W1[(HID + k) * HID + (n - HID)];
        w1 = W1[(HID + k + 1) * HID + (n - HID)];
    }
    int idx = (n >> 6) * SB_ELE + (n & 63) * PITCH + kb;
    g_sB[idx] = pack_h2(w0, w1);
}

// ---------------------------------------------------------------------------
// Precompute: T[n][256] = fp16([emb@W1[:128]+b1 | emb@W1[128:]])
// Single-pass fp16 MMA, fp32 accumulate. A loaded once per CTA (128 rows x
// K=128), loop 4 N-tiles of 64; B tiles block-copied from staging.
// 8 warps = 4(M) x 2(N), warp tile 32x32. ldmatrix.x4 fragment loads.
// smem = 52 KB -> 4 CTAs/SM.
// ---------------------------------------------------------------------------
#define BLOCK_M 128
#define SA_ELE (BLOCK_M * PITCH)       // 8704 b32
#define SMEM_BYTES ((SA_ELE + SB_ELE) * 4)   // 52224 B

__global__ void __launch_bounds__(256, 4) precompute_kernel(
    const float* __restrict__ emb, const float* __restrict__ b1, int n_nodes)
{
    extern __shared__ uint32_t sm[];
    uint32_t* sA = sm;
    uint32_t* sB = sm + SA_ELE;

    const int tid = threadIdx.x;
    const int m0 = blockIdx.x * BLOCK_M;

    // ---- A tile: 128 rows x 128 K floats -> fp16 pairs (once) ----
    for (int i = tid; i < BLOCK_M * (HID / 4); i += 256) {
        int row = i >> 5;
        int c4 = (i & 31) * 4;
        float4 v = make_float4(0.f, 0.f, 0.f, 0.f);
        if (m0 + row < n_nodes)
            v = *reinterpret_cast<const float4*>(emb + (size_t)(m0 + row) * HID + c4);
        int base = row * PITCH + c4 / 2;
        sA[base]     = pack_h2(v.x, v.y);
        sA[base + 1] = pack_h2(v.z, v.w);
    }

    const int warp = tid >> 5, lane = tid & 31;
    const int wm = warp & 3;    // 4 M slabs of 32 rows
    const int wn = warp >> 2;   // 2 N slabs of 32 cols
    const int gid = lane >> 2, tig = lane & 3;

    const int a_row = (lane & 15);
    const int a_kb  = (lane >> 4) * 4;
    const int b_n  = (lane & 7) + (lane >> 4) * 8;
    const int b_kb = ((lane >> 3) & 1) * 4;

    const uint32_t sA_a = smem_u32(sA), sB_a = smem_u32(sB);

    for (int nt = 0; nt < 4; nt++) {
        // ---- copy staged B tile (pure uint4 copies from L2) ----
        {
            const uint4* s = reinterpret_cast<const uint4*>(g_sB + nt * SB_ELE);
            uint4* d = reinterpret_cast<uint4*>(sB);
            for (int i = tid; i < SB_ELE / 4; i += 256)
                d[i] = s[i];
        }
        __syncthreads();

        float acc[2][4][4];
#pragma unroll
        for (int mi = 0; mi < 2; mi++)
#pragma unroll
            for (int ni = 0; ni < 4; ni++)
#pragma unroll
                for (int q = 0; q < 4; q++) acc[mi][ni][q] = 0.f;

#pragma unroll
        for (int ks = 0; ks < HID / 16; ks++) {
            const int kb0 = ks * 8;
            uint32_t af[2][4], bf[2][4];
#pragma unroll
            for (int mi = 0; mi < 2; mi++) {
                uint32_t off = ((wm * 32 + mi * 16 + a_row) * PITCH + kb0 + a_kb) * 4u;
                ldsm_x4(af[mi], sA_a + off);
            }
#pragma unroll
            for (int pr = 0; pr < 2; pr++) {
                uint32_t off = ((wn * 32 + pr * 16 + b_n) * PITCH + kb0 + b_kb) * 4u;
                ldsm_x4(bf[pr], sB_a + off);
            }
#pragma unroll
            for (int mi = 0; mi < 2; mi++)
#pragma unroll
                for (int ni = 0; ni < 4; ni++)
                    mma_f16(acc[mi][ni], af[mi], &bf[ni >> 1][(ni & 1) * 2]);
        }

        // ---- epilogue: +b1 for cols < 128, fp16 pack, 4B stores ----
#pragma unroll
        for (int mi = 0; mi < 2; mi++) {
#pragma unroll
            for (int ni = 0; ni < 4; ni++) {
                int gcol = nt * 64 + wn * 32 + ni * 8 + 2 * tig;
                float add0 = 0.f, add1 = 0.f;
                if (gcol < HID) {
                    add0 = __ldg(b1 + gcol);
                    add1 = __ldg(b1 + gcol + 1);
                }
                int row = m0 + wm * 32 + mi * 16 + gid;
                if (row < n_nodes) {
                    __half2 h = __floats2half2_rn(acc[mi][ni][0] + add0, acc[mi][ni][1] + add1);
                    *reinterpret_cast<__half2*>(&g_table[(size_t)row * 256 + gcol]) = h;
                }
                if (row + 8 < n_nodes) {
                    __half2 h = __floats2half2_rn(acc[mi][ni][2] + add0, acc[mi][ni][3] + add1);
                    *reinterpret_cast<__half2*>(&g_table[(size_t)(row + 8) * 256 + gcol]) = h;
                }
            }
        }
        __syncthreads();   // all MMA reads of B done before next tile's copy
    }
}

// ---------------------------------------------------------------------------
// Index width detection (int64 declared, but JAX w/o x64 emits int32).
// ---------------------------------------------------------------------------
__global__ void detect_kernel(const uint32_t* __restrict__ s) {
    if (threadIdx.x == 0 && blockIdx.x == 0) {
        int is64 = 1;
        for (int i = 1; i < 32; i += 2)
            if (s[i] != 0u) { is64 = 0; break; }
        g_is64 = is64;
    }
}

// ---------------------------------------------------------------------------
// Edge kernel: half-warp (16 lanes) per edge, 4 edges per warp,
// uint4 (16B) gathers. relu via HADD2+HMAX2, dot in fp32.
// ---------------------------------------------------------------------------
__device__ __forceinline__ __half2 u2h(uint32_t x) {
    return *reinterpret_cast<__half2*>(&x);
}

__device__ __forceinline__ float dot8_relu(uint4 a, uint4 c, float4 w0, float4 w1) {
    const __half2 z = __float2half2_rn(0.f);
    __half2 r0 = __hmax2(__hadd2(u2h(a.x), u2h(c.x)), z);
    __half2 r1 = __hmax2(__hadd2(u2h(a.y), u2h(c.y)), z);
    __half2 r2 = __hmax2(__hadd2(u2h(a.z), u2h(c.z)), z);
    __half2 r3 = __hmax2(__hadd2(u2h(a.w), u2h(c.w)), z);
    float2 f0 = __half22float2(r0);
    float2 f1 = __half22float2(r1);
    float2 f2 = __half22float2(r2);
    float2 f3 = __half22float2(r3);
    float s = fmaf(f0.x, w0.x, fmaf(f0.y, w0.y, fmaf(f1.x, w0.z, f1.y * w0.w)));
    s = fmaf(f2.x, w1.x, fmaf(f2.y, w1.y, fmaf(f3.x, w1.z, fmaf(f3.y, w1.w, s))));
    return s;
}

__global__ void __launch_bounds__(256) edge_kernel(
    const void* __restrict__ srcv, const void* __restrict__ tgtv,
    const float* __restrict__ W2, const float* __restrict__ b2,
    float* __restrict__ out, int E)
{
    int gw = (int)((blockIdx.x * blockDim.x + threadIdx.x) >> 5);
    int base = gw * 4;
    if (base >= E) return;
    int lane = threadIdx.x & 31;
    int half = lane >> 4, l16 = lane & 15;

    int ea = base + half * 2;
    int eb = ea + 1;
    bool va = ea < E, vb = eb < E;
    int la = va ? ea : 0;
    int lb = vb ? eb : 0;

    long long sa, ta, sb, tb;
    if (g_is64) {
        const long long* sp = (const long long*)srcv;
        const long long* tp = (const long long*)tgtv;
        sa = sp[la]; ta = tp[la]; sb = sp[lb]; tb = tp[lb];
    } else {
        const int* sp = (const int*)srcv;
        const int* tp = (const int*)tgtv;
        sa = sp[la]; ta = tp[la]; sb = sp[lb]; tb = tp[lb];
    }

    const uint4 Aa = *reinterpret_cast<const uint4*>(&g_table[(size_t)sa * 256 + l16 * 8]);
    const uint4 Ca = *reinterpret_cast<const uint4*>(&g_table[(size_t)ta * 256 + 128 + l16 * 8]);
    const uint4 Ab = *reinterpret_cast<const uint4*>(&g_table[(size_t)sb * 256 + l16 * 8]);
    const uint4 Cb = *reinterpret_cast<const uint4*>(&g_table[(size_t)tb * 256 + 128 + l16 * 8]);
    const float4 w0 = *reinterpret_cast<const float4*>(W2 + l16 * 8);
    const float4 w1 = *reinterpret_cast<const float4*>(W2 + l16 * 8 + 4);

    float suma = dot8_relu(Aa, Ca, w0, w1);
    float sumb = dot8_relu(Ab, Cb, w0, w1);

#pragma unroll
    for (int off = 8; off; off >>= 1) {
        suma += __shfl_xor_sync(0xFFFFFFFFu, suma, off);
        sumb += __shfl_xor_sync(0xFFFFFFFFu, sumb, off);
    }

    if (l16 == 0) {
        float bias = __ldg(b2);
        if (va) out[ea] = suma + bias;
        if (vb) out[eb] = sumb + bias;
    }
}

// ---------------------------------------------------------------------------
// launch
// ---------------------------------------------------------------------------
extern "C" void kernel_launch(void* const* d_in, const int* in_sizes, int n_in,
                              void* d_out, int out_size)
{
    const float* emb = (const float*)d_in[0];
    const void* src = d_in[1];
    const void* tgt = d_in[2];

    int base = (n_in > 3 && in_sizes[3] == 2 * HID * HID) ? 3 : 4;
    const float* W1 = (const float*)d_in[base];
    const float* b1 = (const float*)d_in[base + 1];
    const float* W2 = (const float*)d_in[base + 2];
    const float* b2 = (const float*)d_in[base + 3];

    int n_nodes = in_sizes[0] / HID;
    int E = in_sizes[1];

    prep_w1_kernel<<<64, 256>>>(W1);

    cudaFuncSetAttribute(precompute_kernel,
                         cudaFuncAttributeMaxDynamicSharedMemorySize, SMEM_BYTES);
    int pgrid = (n_nodes + BLOCK_M - 1) / BLOCK_M;
    precompute_kernel<<<pgrid, 256, SMEM_BYTES>>>(emb, b1, n_nodes);

    detect_kernel<<<1, 32>>>((const uint32_t*)src);

    // 8 warps/block, 4 edges/warp
    int warps_needed = (E + 3) / 4;
    int nblocks = (warps_needed + 7) / 8;
    edge_kernel<<<nblocks, 256>>>(src, tgt, W2, b2, (float*)d_out, E);
}

// round 7
// speedup vs baseline: 4.1880x; 1.1034x over previous
#include <cuda_runtime.h>
#include <cuda_fp16.h>
#include <cuda_bf16.h>
#include <cstdint>
#include <cstddef>

#define HID 128
#define MAX_NODES 100096

// fp16 table: row n = [fp16(emb[n]@W1[:128]+b1) | fp16(emb[n]@W1[128:])]
__device__ __half g_table[(size_t)MAX_NODES * 256];
__device__ __half g_W2h[HID];
__device__ int g_is64;

#define PITCH 68
#define SB_ELE (64 * PITCH)            // 4352 b32 per 64-col N-tile
// staged fp16 W1 in the exact padded smem layout, 4 N-tiles of 64
__device__ uint32_t g_sB[4 * SB_ELE];

// ---------------------------------------------------------------------------
// helpers
// ---------------------------------------------------------------------------
__device__ __forceinline__ uint32_t smem_u32(const void* p) {
    uint32_t a;
    asm("{ .reg .u64 t; cvta.to.shared.u64 t, %1; cvt.u32.u64 %0, t; }" : "=r"(a) : "l"(p));
    return a;
}

__device__ __forceinline__ uint32_t pack_h2(float x0, float x1) {
    __half2 p = __floats2half2_rn(x0, x1);  // .x -> low half
    return *reinterpret_cast<uint32_t*>(&p);
}

__device__ __forceinline__ void mma_f16(float* d, const uint32_t* a, const uint32_t* b) {
    asm volatile(
        "mma.sync.aligned.m16n8k16.row.col.f32.f16.f16.f32 "
        "{%0,%1,%2,%3}, {%4,%5,%6,%7}, {%8,%9}, {%0,%1,%2,%3};\n"
        : "+f"(d[0]), "+f"(d[1]), "+f"(d[2]), "+f"(d[3])
        : "r"(a[0]), "r"(a[1]), "r"(a[2]), "r"(a[3]), "r"(b[0]), "r"(b[1]));
}

__device__ __forceinline__ void ldsm_x4(uint32_t* r, uint32_t addr) {
    asm volatile("ldmatrix.sync.aligned.m8n8.x4.shared.b16 {%0,%1,%2,%3}, [%4];"
                 : "=r"(r[0]), "=r"(r[1]), "=r"(r[2]), "=r"(r[3]) : "r"(addr));
}

// ---------------------------------------------------------------------------
// Prep: W1 -> fp16 staging (padded [n][kb] layout, 4 N-tiles of 64),
// W2 -> fp16, plus index-width detection (one launch for all).
// ---------------------------------------------------------------------------
__global__ void prep_kernel(const float* __restrict__ W1,
                            const float* __restrict__ W2,
                            const uint32_t* __restrict__ src)
{
    int i = blockIdx.x * blockDim.x + threadIdx.x;  // 0..16383
    if (i < 256 * 64) {
        int n = i & 255;
        int kb = i >> 8;             // b32 index along K (k = 2*kb)
        int k = kb * 2;
        float w0, w1;
        if (n < HID) {
            w0 = W1[k * HID + n];
            w1 = W1[(k + 1) * HID + n];
        } else {
            w0 = W1[(HID + k) * HID + (n - HID)];
            w1 = W1[(HID + k + 1) * HID + (n - HID)];
        }
        int idx = (n >> 6) * SB_ELE + (n & 63) * PITCH + kb;
        g_sB[idx] = pack_h2(w0, w1);
    }
    if (i < HID) g_W2h[i] = __float2half_rn(W2[i]);
    if (i == 0) {
        int is64 = 1;
        for (int j = 1; j < 32; j += 2)
            if (src[j] != 0u) { is64 = 0; break; }
        g_is64 = is64;
    }
}

// ---------------------------------------------------------------------------
// Precompute: T[n][256] = fp16([emb@W1[:128]+b1 | emb@W1[128:]])
// Single-pass fp16 MMA, fp32 accumulate. A loaded once per CTA (128 rows x
// K=128), loop 4 N-tiles of 64; B tiles block-copied from staging.
// 8 warps = 4(M) x 2(N), warp tile 32x32. ldmatrix.x4 fragment loads.
// smem = 52 KB -> 4 CTAs/SM.
// ---------------------------------------------------------------------------
#define BLOCK_M 128
#define SA_ELE (BLOCK_M * PITCH)       // 8704 b32
#define SMEM_BYTES ((SA_ELE + SB_ELE) * 4)   // 52224 B

__global__ void __launch_bounds__(256, 4) precompute_kernel(
    const float* __restrict__ emb, const float* __restrict__ b1, int n_nodes)
{
    extern __shared__ uint32_t sm[];
    uint32_t* sA = sm;
    uint32_t* sB = sm + SA_ELE;

    const int tid = threadIdx.x;
    const int m0 = blockIdx.x * BLOCK_M;

    // ---- A tile: 128 rows x 128 K floats -> fp16 pairs (once) ----
    for (int i = tid; i < BLOCK_M * (HID / 4); i += 256) {
        int row = i >> 5;
        int c4 = (i & 31) * 4;
        float4 v = make_float4(0.f, 0.f, 0.f, 0.f);
        if (m0 + row < n_nodes)
            v = *reinterpret_cast<const float4*>(emb + (size_t)(m0 + row) * HID + c4);
        int base = row * PITCH + c4 / 2;
        sA[base]     = pack_h2(v.x, v.y);
        sA[base + 1] = pack_h2(v.z, v.w);
    }

    const int warp = tid >> 5, lane = tid & 31;
    const int wm = warp & 3;    // 4 M slabs of 32 rows
    const int wn = warp >> 2;   // 2 N slabs of 32 cols
    const int gid = lane >> 2, tig = lane & 3;

    const int a_row = (lane & 15);
    const int a_kb  = (lane >> 4) * 4;
    const int b_n  = (lane & 7) + (lane >> 4) * 8;
    const int b_kb = ((lane >> 3) & 1) * 4;

    const uint32_t sA_a = smem_u32(sA), sB_a = smem_u32(sB);

    for (int nt = 0; nt < 4; nt++) {
        // ---- copy staged B tile (pure uint4 copies from L2) ----
        {
            const uint4* s = reinterpret_cast<const uint4*>(g_sB + nt * SB_ELE);
            uint4* d = reinterpret_cast<uint4*>(sB);
            for (int i = tid; i < SB_ELE / 4; i += 256)
                d[i] = s[i];
        }
        __syncthreads();

        float acc[2][4][4];
#pragma unroll
        for (int mi = 0; mi < 2; mi++)
#pragma unroll
            for (int ni = 0; ni < 4; ni++)
#pragma unroll
                for (int q = 0; q < 4; q++) acc[mi][ni][q] = 0.f;

#pragma unroll
        for (int ks = 0; ks < HID / 16; ks++) {
            const int kb0 = ks * 8;
            uint32_t af[2][4], bf[2][4];
#pragma unroll
            for (int mi = 0; mi < 2; mi++) {
                uint32_t off = ((wm * 32 + mi * 16 + a_row) * PITCH + kb0 + a_kb) * 4u;
                ldsm_x4(af[mi], sA_a + off);
            }
#pragma unroll
            for (int pr = 0; pr < 2; pr++) {
                uint32_t off = ((wn * 32 + pr * 16 + b_n) * PITCH + kb0 + b_kb) * 4u;
                ldsm_x4(bf[pr], sB_a + off);
            }
#pragma unroll
            for (int mi = 0; mi < 2; mi++)
#pragma unroll
                for (int ni = 0; ni < 4; ni++)
                    mma_f16(acc[mi][ni], af[mi], &bf[ni >> 1][(ni & 1) * 2]);
        }

        // ---- epilogue: +b1 for cols < 128, fp16 pack, 4B stores ----
#pragma unroll
        for (int mi = 0; mi < 2; mi++) {
#pragma unroll
            for (int ni = 0; ni < 4; ni++) {
                int gcol = nt * 64 + wn * 32 + ni * 8 + 2 * tig;
                float add0 = 0.f, add1 = 0.f;
                if (gcol < HID) {
                    add0 = __ldg(b1 + gcol);
                    add1 = __ldg(b1 + gcol + 1);
                }
                int row = m0 + wm * 32 + mi * 16 + gid;
                if (row < n_nodes) {
                    __half2 h = __floats2half2_rn(acc[mi][ni][0] + add0, acc[mi][ni][1] + add1);
                    *reinterpret_cast<__half2*>(&g_table[(size_t)row * 256 + gcol]) = h;
                }
                if (row + 8 < n_nodes) {
                    __half2 h = __floats2half2_rn(acc[mi][ni][2] + add0, acc[mi][ni][3] + add1);
                    *reinterpret_cast<__half2*>(&g_table[(size_t)(row + 8) * 256 + gcol]) = h;
                }
            }
        }
        __syncthreads();   // all MMA reads of B done before next tile's copy
    }
}

// ---------------------------------------------------------------------------
// Edge kernel: half-warp (16 lanes) per edge, 4 edges per warp,
// uint4 (16B) gathers, 32-bit table offsets. relu via HADD2+HMAX2,
// products via HMUL2/HFMA2 (two depth-2 chains), fp32 combine + reduce.
// ---------------------------------------------------------------------------
__device__ __forceinline__ __half2 u2h(uint32_t x) {
    return *reinterpret_cast<__half2*>(&x);
}

__device__ __forceinline__ float dot8_relu(uint4 a, uint4 c, uint4 w) {
    const __half2 z = __float2half2_rn(0.f);
    __half2 r0 = __hmax2(__hadd2(u2h(a.x), u2h(c.x)), z);
    __half2 r1 = __hmax2(__hadd2(u2h(a.y), u2h(c.y)), z);
    __half2 r2 = __hmax2(__hadd2(u2h(a.z), u2h(c.z)), z);
    __half2 r3 = __hmax2(__hadd2(u2h(a.w), u2h(c.w)), z);
    __half2 p0 = __hmul2(r0, u2h(w.x));
    p0 = __hfma2(r1, u2h(w.y), p0);
    __half2 p1 = __hmul2(r2, u2h(w.z));
    p1 = __hfma2(r3, u2h(w.w), p1);
    float2 f0 = __half22float2(p0);
    float2 f1 = __half22float2(p1);
    return (f0.x + f0.y) + (f1.x + f1.y);
}

__global__ void __launch_bounds__(256) edge_kernel(
    const void* __restrict__ srcv, const void* __restrict__ tgtv,
    const float* __restrict__ b2, float* __restrict__ out, int E)
{
    int gw = (int)((blockIdx.x * blockDim.x + threadIdx.x) >> 5);
    int base = gw * 4;
    if (base >= E) return;
    int lane = threadIdx.x & 31;
    int half = lane >> 4, l16 = lane & 15;

    int ea = base + half * 2;
    int eb = ea + 1;
    bool va = ea < E, vb = eb < E;
    int la = va ? ea : 0;
    int lb = vb ? eb : 0;

    uint32_t sa, ta, sb, tb;  // node ids < 2^17, 32-bit is plenty
    if (g_is64) {
        const long long* sp = (const long long*)srcv;
        const long long* tp = (const long long*)tgtv;
        sa = (uint32_t)sp[la]; ta = (uint32_t)tp[la];
        sb = (uint32_t)sp[lb]; tb = (uint32_t)tp[lb];
    } else {
        const uint32_t* sp = (const uint32_t*)srcv;
        const uint32_t* tp = (const uint32_t*)tgtv;
        sa = sp[la]; ta = tp[la]; sb = sp[lb]; tb = tp[lb];
    }

    const __half* tab = g_table;
    const uint32_t col = (uint32_t)(l16 * 8);
    const uint4 Aa = *reinterpret_cast<const uint4*>(tab + sa * 256u + col);
    const uint4 Ca = *reinterpret_cast<const uint4*>(tab + ta * 256u + 128u + col);
    const uint4 Ab = *reinterpret_cast<const uint4*>(tab + sb * 256u + col);
    const uint4 Cb = *reinterpret_cast<const uint4*>(tab + tb * 256u + 128u + col);
    const uint4 w = *reinterpret_cast<const uint4*>(g_W2h + col);

    float suma = dot8_relu(Aa, Ca, w);
    float sumb = dot8_relu(Ab, Cb, w);

#pragma unroll
    for (int off = 8; off; off >>= 1) {
        suma += __shfl_xor_sync(0xFFFFFFFFu, suma, off);
        sumb += __shfl_xor_sync(0xFFFFFFFFu, sumb, off);
    }

    if (l16 == 0) {
        float bias = __ldg(b2);
        if (va) out[ea] = suma + bias;
        if (vb) out[eb] = sumb + bias;
    }
}

// ---------------------------------------------------------------------------
// launch
// ---------------------------------------------------------------------------
extern "C" void kernel_launch(void* const* d_in, const int* in_sizes, int n_in,
                              void* d_out, int out_size)
{
    const float* emb = (const float*)d_in[0];
    const void* src = d_in[1];
    const void* tgt = d_in[2];

    int base = (n_in > 3 && in_sizes[3] == 2 * HID * HID) ? 3 : 4;
    const float* W1 = (const float*)d_in[base];
    const float* b1 = (const float*)d_in[base + 1];
    const float* W2 = (const float*)d_in[base + 2];
    const float* b2 = (const float*)d_in[base + 3];

    int n_nodes = in_sizes[0] / HID;
    int E = in_sizes[1];

    prep_kernel<<<64, 256>>>(W1, W2, (const uint32_t*)src);

    cudaFuncSetAttribute(precompute_kernel,
                         cudaFuncAttributeMaxDynamicSharedMemorySize, SMEM_BYTES);
    int pgrid = (n_nodes + BLOCK_M - 1) / BLOCK_M;
    precompute_kernel<<<pgrid, 256, SMEM_BYTES>>>(emb, b1, n_nodes);

    // 8 warps/block, 4 edges/warp
    int warps_needed = (E + 3) / 4;
    int nblocks = (warps_needed + 7) / 8;
    edge_kernel<<<nblocks, 256>>>(src, tgt, b2, (float*)d_out, E);
}

// round 8
// speedup vs baseline: 4.4688x; 1.0670x over previous
#include <cuda_runtime.h>
#include <cuda_fp16.h>
#include <cuda_bf16.h>
#include <cstdint>
#include <cstddef>

#define HID 128
#define MAX_NODES 100096

// fp16 table: row n = [fp16(emb[n]@W1[:128]+b1) | fp16(emb[n]@W1[128:])]
__device__ __half g_table[(size_t)MAX_NODES * 256];
__device__ __half g_W2h[HID];
__device__ int g_is64;

#define PITCH 68
#define SB_ELE (64 * PITCH)            // 4352 b32 per 64-col N-tile
// staged fp16 W1 in the exact padded smem layout, 4 N-tiles of 64
__device__ uint32_t g_sB[4 * SB_ELE];

// ---------------------------------------------------------------------------
// helpers
// ---------------------------------------------------------------------------
__device__ __forceinline__ uint32_t smem_u32(const void* p) {
    uint32_t a;
    asm("{ .reg .u64 t; cvta.to.shared.u64 t, %1; cvt.u32.u64 %0, t; }" : "=r"(a) : "l"(p));
    return a;
}

__device__ __forceinline__ uint32_t pack_h2(float x0, float x1) {
    __half2 p = __floats2half2_rn(x0, x1);  // .x -> low half
    return *reinterpret_cast<uint32_t*>(&p);
}

__device__ __forceinline__ void mma_f16(float* d, const uint32_t* a, const uint32_t* b) {
    asm volatile(
        "mma.sync.aligned.m16n8k16.row.col.f32.f16.f16.f32 "
        "{%0,%1,%2,%3}, {%4,%5,%6,%7}, {%8,%9}, {%0,%1,%2,%3};\n"
        : "+f"(d[0]), "+f"(d[1]), "+f"(d[2]), "+f"(d[3])
        : "r"(a[0]), "r"(a[1]), "r"(a[2]), "r"(a[3]), "r"(b[0]), "r"(b[1]));
}

__device__ __forceinline__ void ldsm_x4(uint32_t* r, uint32_t addr) {
    asm volatile("ldmatrix.sync.aligned.m8n8.x4.shared.b16 {%0,%1,%2,%3}, [%4];"
                 : "=r"(r[0]), "=r"(r[1]), "=r"(r[2]), "=r"(r[3]) : "r"(addr));
}

// ---------------------------------------------------------------------------
// Prep: W1 -> fp16 staging (padded [n][kb] layout, 4 N-tiles of 64),
// W2 -> fp16, plus index-width detection (one launch for all).
// ---------------------------------------------------------------------------
__global__ void prep_kernel(const float* __restrict__ W1,
                            const float* __restrict__ W2,
                            const uint32_t* __restrict__ src)
{
    int i = blockIdx.x * blockDim.x + threadIdx.x;  // 0..16383
    if (i < 256 * 64) {
        int n = i & 255;
        int kb = i >> 8;             // b32 index along K (k = 2*kb)
        int k = kb * 2;
        float w0, w1;
        if (n < HID) {
            w0 = W1[k * HID + n];
            w1 = W1[(k + 1) * HID + n];
        } else {
            w0 = W1[(HID + k) * HID + (n - HID)];
            w1 = W1[(HID + k + 1) * HID + (n - HID)];
        }
        int idx = (n >> 6) * SB_ELE + (n & 63) * PITCH + kb;
        g_sB[idx] = pack_h2(w0, w1);
    }
    if (i < HID) g_W2h[i] = __float2half_rn(W2[i]);
    if (i == 0) {
        int is64 = 1;
        for (int j = 1; j < 32; j += 2)
            if (src[j] != 0u) { is64 = 0; break; }
        g_is64 = is64;
    }
}

// ---------------------------------------------------------------------------
// Precompute: T[n][256] = fp16([emb@W1[:128]+b1 | emb@W1[128:]])
// Single-pass fp16 MMA, fp32 accumulate, b1 folded into acc init.
// A loaded once per CTA (128 rows x K=128), loop 4 N-tiles of 64.
// 8 warps = 4(M) x 2(N), warp tile 32x32. ldmatrix.x4 fragment loads.
// ---------------------------------------------------------------------------
#define BLOCK_M 128
#define SA_ELE (BLOCK_M * PITCH)       // 8704 b32
#define SM_B1_OFF (SA_ELE + SB_ELE)    // b32 offset of b1 (128 floats)
#define SMEM_BYTES ((SA_ELE + SB_ELE + HID) * 4)   // 52736 B -> 4 CTAs/SM

__global__ void __launch_bounds__(256, 4) precompute_kernel(
    const float* __restrict__ emb, const float* __restrict__ b1, int n_nodes)
{
    extern __shared__ uint32_t sm[];
    uint32_t* sA = sm;
    uint32_t* sB = sm + SA_ELE;
    float* sb1 = reinterpret_cast<float*>(sm + SM_B1_OFF);

    const int tid = threadIdx.x;
    const int m0 = blockIdx.x * BLOCK_M;

    if (tid < HID) sb1[tid] = b1[tid];

    // ---- A tile: 128 rows x 128 K floats -> fp16 pairs (once) ----
    for (int i = tid; i < BLOCK_M * (HID / 4); i += 256) {
        int row = i >> 5;
        int c4 = (i & 31) * 4;
        float4 v = make_float4(0.f, 0.f, 0.f, 0.f);
        if (m0 + row < n_nodes)
            v = *reinterpret_cast<const float4*>(emb + (size_t)(m0 + row) * HID + c4);
        int base = row * PITCH + c4 / 2;
        sA[base]     = pack_h2(v.x, v.y);
        sA[base + 1] = pack_h2(v.z, v.w);
    }

    const int warp = tid >> 5, lane = tid & 31;
    const int wm = warp & 3;    // 4 M slabs of 32 rows
    const int wn = warp >> 2;   // 2 N slabs of 32 cols
    const int gid = lane >> 2, tig = lane & 3;

    const int a_row = (lane & 15);
    const int a_kb  = (lane >> 4) * 4;
    const int b_n  = (lane & 7) + (lane >> 4) * 8;
    const int b_kb = ((lane >> 3) & 1) * 4;

    const uint32_t sA_a = smem_u32(sA), sB_a = smem_u32(sB);

    for (int nt = 0; nt < 4; nt++) {
        // ---- copy staged B tile (pure uint4 copies from L2) ----
        {
            const uint4* s = reinterpret_cast<const uint4*>(g_sB + nt * SB_ELE);
            uint4* d = reinterpret_cast<uint4*>(sB);
            for (int i = tid; i < SB_ELE / 4; i += 256)
                d[i] = s[i];
        }
        __syncthreads();

        // ---- acc init: b1 for cols < 128, else 0 ----
        float acc[2][4][4];
#pragma unroll
        for (int ni = 0; ni < 4; ni++) {
            int gcol = nt * 64 + wn * 32 + ni * 8 + 2 * tig;
            float c0 = 0.f, c1 = 0.f;
            if (gcol < HID) {
                float2 bb = *reinterpret_cast<const float2*>(sb1 + gcol);
                c0 = bb.x; c1 = bb.y;
            }
#pragma unroll
            for (int mi = 0; mi < 2; mi++) {
                acc[mi][ni][0] = c0; acc[mi][ni][1] = c1;
                acc[mi][ni][2] = c0; acc[mi][ni][3] = c1;
            }
        }

#pragma unroll
        for (int ks = 0; ks < HID / 16; ks++) {
            const int kb0 = ks * 8;
            uint32_t af[2][4], bf[2][4];
#pragma unroll
            for (int mi = 0; mi < 2; mi++) {
                uint32_t off = ((wm * 32 + mi * 16 + a_row) * PITCH + kb0 + a_kb) * 4u;
                ldsm_x4(af[mi], sA_a + off);
            }
#pragma unroll
            for (int pr = 0; pr < 2; pr++) {
                uint32_t off = ((wn * 32 + pr * 16 + b_n) * PITCH + kb0 + b_kb) * 4u;
                ldsm_x4(bf[pr], sB_a + off);
            }
#pragma unroll
            for (int mi = 0; mi < 2; mi++)
#pragma unroll
                for (int ni = 0; ni < 4; ni++)
                    mma_f16(acc[mi][ni], af[mi], &bf[ni >> 1][(ni & 1) * 2]);
        }

        // ---- epilogue: fp16 pack, 4B stores ----
#pragma unroll
        for (int mi = 0; mi < 2; mi++) {
#pragma unroll
            for (int ni = 0; ni < 4; ni++) {
                int gcol = nt * 64 + wn * 32 + ni * 8 + 2 * tig;
                int row = m0 + wm * 32 + mi * 16 + gid;
                if (row < n_nodes) {
                    __half2 h = __floats2half2_rn(acc[mi][ni][0], acc[mi][ni][1]);
                    *reinterpret_cast<__half2*>(&g_table[(size_t)row * 256 + gcol]) = h;
                }
                if (row + 8 < n_nodes) {
                    __half2 h = __floats2half2_rn(acc[mi][ni][2], acc[mi][ni][3]);
                    *reinterpret_cast<__half2*>(&g_table[(size_t)(row + 8) * 256 + gcol]) = h;
                }
            }
        }
        __syncthreads();   // all MMA reads of B done before next tile's copy
    }
}

// ---------------------------------------------------------------------------
// Edge kernel: 8 edges per warp (half-warp owns 4 consecutive edges).
// Vectorized index loads, 8 LDG.128 gathers in flight per thread,
// hfma2_relu fused add+relu, fp32 reduce, coalesced float4 result store.
// ---------------------------------------------------------------------------
__device__ __forceinline__ __half2 u2h(uint32_t x) {
    return *reinterpret_cast<__half2*>(&x);
}

__device__ __forceinline__ float dot8_relu(uint4 a, uint4 c, uint4 w) {
    const __half2 one = __float2half2_rn(1.f);
    __half2 r0 = __hfma2_relu(u2h(a.x), one, u2h(c.x));
    __half2 r1 = __hfma2_relu(u2h(a.y), one, u2h(c.y));
    __half2 r2 = __hfma2_relu(u2h(a.z), one, u2h(c.z));
    __half2 r3 = __hfma2_relu(u2h(a.w), one, u2h(c.w));
    __half2 p0 = __hmul2(r0, u2h(w.x));
    p0 = __hfma2(r1, u2h(w.y), p0);
    __half2 p1 = __hmul2(r2, u2h(w.z));
    p1 = __hfma2(r3, u2h(w.w), p1);
    float2 f0 = __half22float2(p0);
    float2 f1 = __half22float2(p1);
    return (f0.x + f0.y) + (f1.x + f1.y);
}

__global__ void __launch_bounds__(256) edge_kernel(
    const void* __restrict__ srcv, const void* __restrict__ tgtv,
    const float* __restrict__ b2, float* __restrict__ out, int E)
{
    int gw = (int)((blockIdx.x * blockDim.x + threadIdx.x) >> 5);
    int base = gw * 8;
    if (base >= E) return;
    int lane = threadIdx.x & 31;
    int half = lane >> 4, l16 = lane & 15;

    int e0 = base + half * 4;             // this half's first edge (mult of 4)
    bool full = (e0 + 4 <= E);

    uint32_t s[4], t[4];
    if (g_is64) {
        const long long* sp = (const long long*)srcv;
        const long long* tp = (const long long*)tgtv;
        if (full) {
            longlong2 s01 = *reinterpret_cast<const longlong2*>(sp + e0);
            longlong2 s23 = *reinterpret_cast<const longlong2*>(sp + e0 + 2);
            longlong2 t01 = *reinterpret_cast<const longlong2*>(tp + e0);
            longlong2 t23 = *reinterpret_cast<const longlong2*>(tp + e0 + 2);
            s[0] = (uint32_t)s01.x; s[1] = (uint32_t)s01.y;
            s[2] = (uint32_t)s23.x; s[3] = (uint32_t)s23.y;
            t[0] = (uint32_t)t01.x; t[1] = (uint32_t)t01.y;
            t[2] = (uint32_t)t23.x; t[3] = (uint32_t)t23.y;
        } else {
#pragma unroll
            for (int e = 0; e < 4; e++) {
                int idx = (e0 + e < E) ? e0 + e : E - 1;
                s[e] = (uint32_t)sp[idx];
                t[e] = (uint32_t)tp[idx];
            }
        }
    } else {
        const int* sp = (const int*)srcv;
        const int* tp = (const int*)tgtv;
        if (full) {
            uint4 sv = *reinterpret_cast<const uint4*>(sp + e0);
            uint4 tv = *reinterpret_cast<const uint4*>(tp + e0);
            s[0] = sv.x; s[1] = sv.y; s[2] = sv.z; s[3] = sv.w;
            t[0] = tv.x; t[1] = tv.y; t[2] = tv.z; t[3] = tv.w;
        } else {
#pragma unroll
            for (int e = 0; e < 4; e++) {
                int idx = (e0 + e < E) ? e0 + e : E - 1;
                s[e] = (uint32_t)sp[idx];
                t[e] = (uint32_t)tp[idx];
            }
        }
    }

    const __half* tab = g_table;
    const uint32_t col = (uint32_t)(l16 * 8);
    uint4 A[4], C[4];
#pragma unroll
    for (int e = 0; e < 4; e++) {
        A[e] = *reinterpret_cast<const uint4*>(tab + s[e] * 256u + col);
        C[e] = *reinterpret_cast<const uint4*>(tab + t[e] * 256u + 128u + col);
    }
    const uint4 w = *reinterpret_cast<const uint4*>(g_W2h + col);

    float sum[4];
#pragma unroll
    for (int e = 0; e < 4; e++)
        sum[e] = dot8_relu(A[e], C[e], w);

#pragma unroll
    for (int off = 8; off; off >>= 1) {
#pragma unroll
        for (int e = 0; e < 4; e++)
            sum[e] += __shfl_xor_sync(0xFFFFFFFFu, sum[e], off);
    }

    if (l16 == 0) {
        float bias = __ldg(b2);
        if (full) {
            float4 r = make_float4(sum[0] + bias, sum[1] + bias,
                                   sum[2] + bias, sum[3] + bias);
            *reinterpret_cast<float4*>(out + e0) = r;
        } else {
#pragma unroll
            for (int e = 0; e < 4; e++)
                if (e0 + e < E) out[e0 + e] = sum[e] + bias;
        }
    }
}

// ---------------------------------------------------------------------------
// launch
// ---------------------------------------------------------------------------
extern "C" void kernel_launch(void* const* d_in, const int* in_sizes, int n_in,
                              void* d_out, int out_size)
{
    const float* emb = (const float*)d_in[0];
    const void* src = d_in[1];
    const void* tgt = d_in[2];

    int base = (n_in > 3 && in_sizes[3] == 2 * HID * HID) ? 3 : 4;
    const float* W1 = (const float*)d_in[base];
    const float* b1 = (const float*)d_in[base + 1];
    const float* W2 = (const float*)d_in[base + 2];
    const float* b2 = (const float*)d_in[base + 3];

    int n_nodes = in_sizes[0] / HID;
    int E = in_sizes[1];

    prep_kernel<<<64, 256>>>(W1, W2, (const uint32_t*)src);

    cudaFuncSetAttribute(precompute_kernel,
                         cudaFuncAttributeMaxDynamicSharedMemorySize, SMEM_BYTES);
    int pgrid = (n_nodes + BLOCK_M - 1) / BLOCK_M;
    precompute_kernel<<<pgrid, 256, SMEM_BYTES>>>(emb, b1, n_nodes);

    // 8 warps/block, 8 edges/warp
    int warps_needed = (E + 7) / 8;
    int nblocks = (warps_needed + 7) / 8;
    edge_kernel<<<nblocks, 256>>>(src, tgt, b2, (float*)d_out, E);
}